// round 15
// baseline (speedup 1.0000x reference)
#include <cuda_runtime.h>
#include <cstdint>

#define T_BATCH 256
#define D_IN    784
#define M_      800
#define N_      8
#define K_      25
#define MN_     6400
#define NEG_INF (-3.402823466e38f)
#define POS_INF (3.402823466e38f)

// Scratch (allocation-free rule: __device__ globals)
__device__ float g_WbT[(size_t)MN_ * MN_];     // W_b^T, rows sigma-permuted (164 MB)
__device__ float g_Abb[(size_t)T_BATCH * MN_]; // abb[t][sig(j)] = a[t][j%800]+bb[j]
__device__ float g_WdT[M_ * D_IN];             // W_d transposed

// Within-row permutation: j = 16q + 4k + i  ->  pos = 1600k + 4q + i.
// Thread q owns 16 consecutive j via 4 coalesced float4 loads at
// positions {q, 400+q, 800+q, 1200+q}.
__device__ __forceinline__ int sig(int j) {
    return ((j >> 2) & 3) * 1600 + ((j >> 4) << 2) + (j & 3);
}

// Monotone float<->uint order mapping (no NaNs in this workload)
__device__ __forceinline__ unsigned fmap(unsigned b) {
    return (b & 0x80000000u) ? ~b : (b | 0x80000000u);
}
__device__ __forceinline__ float funmap(unsigned u) {
    unsigned b = (u & 0x80000000u) ? (u & 0x7FFFFFFFu) : ~u;
    return __uint_as_float(b);
}

// ---------------------------------------------------------------------------
// Mega prep kernel (layout-permuted stores; same DRAM byte totals)
// ---------------------------------------------------------------------------
#define GEMM_BLKS 200
#define WD_BLKS   625
#define WB_BASE   (GEMM_BLKS + WD_BLKS)
#define PREP_BLKS (WB_BASE + 200 * 200)
#define TS 36   // 144B row stride: 16B-aligned rows for float4 LDS/STS

__global__ void __launch_bounds__(256)
prep_kernel(const float* __restrict__ X, const float* __restrict__ Wa,
            const float* __restrict__ ba, const float* __restrict__ Wd,
            const float* __restrict__ Wb, const float* __restrict__ bb) {
    __shared__ __align__(16) float sh[2 * 32 * TS];
    const int b = blockIdx.x;
    const int tid = threadIdx.x;

    if (b >= WB_BASE) {
        // W_b transpose with sigma-permuted in-row (j) index
        float (*tile)[33] = (float(*)[33])sh;
        int b2 = b - WB_BASE;
        int bx = b2 % 200, by = b2 / 200;
        int tx = tid & 31, ty = tid >> 5;
        int x = bx * 32 + tx;
        int y0 = by * 32;
#pragma unroll
        for (int i = ty; i < 32; i += 8)
            tile[i][tx] = Wb[(size_t)(y0 + i) * MN_ + x];
        __syncthreads();
        int x2 = by * 32 + tx;       // in-row (j) index before permutation
        int y2 = bx * 32;            // row (W column) index
        int px = sig(x2);
#pragma unroll
        for (int i = ty; i < 32; i += 8)
            g_WbT[(size_t)(y2 + i) * MN_ + px] = tile[tx][i];
    } else if (b < GEMM_BLKS) {
        float (*Xs)[TS] = (float(*)[TS])sh;
        float (*Ws)[TS] = (float(*)[TS])(sh + 32 * TS);
        const int bm = b % 25, bt = b / 25;
        const int lrow = tid >> 3, lc4 = tid & 7;
        const int tx = tid & 15, ty = tid >> 4;
        float c00 = 0.f, c01 = 0.f, c10 = 0.f, c11 = 0.f;
        for (int k0 = 0; k0 < D_IN; k0 += 32) {
            int kc = k0 + lc4 * 4;
            float4 xv = (kc + 3 < D_IN)
                ? *(const float4*)(X + (bt * 32 + lrow) * D_IN + kc)
                : make_float4(0.f, 0.f, 0.f, 0.f);
            float4 wv = (kc + 3 < D_IN)
                ? *(const float4*)(Wa + (bm * 32 + lrow) * D_IN + kc)
                : make_float4(0.f, 0.f, 0.f, 0.f);
            __syncthreads();
            *(float4*)&Xs[lrow][lc4 * 4] = xv;
            *(float4*)&Ws[lrow][lc4 * 4] = wv;
            __syncthreads();
#pragma unroll
            for (int k = 0; k < 32; k += 4) {
                float4 x0 = *(const float4*)&Xs[2 * ty][k];
                float4 x1 = *(const float4*)&Xs[2 * ty + 1][k];
                float4 w0 = *(const float4*)&Ws[2 * tx][k];
                float4 w1 = *(const float4*)&Ws[2 * tx + 1][k];
                c00 = fmaf(x0.x, w0.x, c00); c00 = fmaf(x0.y, w0.y, c00);
                c00 = fmaf(x0.z, w0.z, c00); c00 = fmaf(x0.w, w0.w, c00);
                c01 = fmaf(x0.x, w1.x, c01); c01 = fmaf(x0.y, w1.y, c01);
                c01 = fmaf(x0.z, w1.z, c01); c01 = fmaf(x0.w, w1.w, c01);
                c10 = fmaf(x1.x, w0.x, c10); c10 = fmaf(x1.y, w0.y, c10);
                c10 = fmaf(x1.z, w0.z, c10); c10 = fmaf(x1.w, w0.w, c10);
                c11 = fmaf(x1.x, w1.x, c11); c11 = fmaf(x1.y, w1.y, c11);
                c11 = fmaf(x1.z, w1.z, c11); c11 = fmaf(x1.w, w1.w, c11);
            }
        }
        int m0 = bm * 32 + 2 * tx, t0 = bt * 32 + 2 * ty;   // m0 even
        float a00 = c00 + ba[m0],     a01 = c01 + ba[m0 + 1];
        float a10 = c10 + ba[m0],     a11 = c11 + ba[m0 + 1];
#pragma unroll
        for (int k = 0; k < 8; ++k) {
            int j0 = m0 + 800 * k;
            int p0 = sig(j0);            // sig(j0+1) == p0+1 (j0 even)
            float b0 = bb[j0], b1 = bb[j0 + 1];
            g_Abb[(size_t)t0 * MN_ + p0]           = a00 + b0;
            g_Abb[(size_t)t0 * MN_ + p0 + 1]       = a01 + b1;
            g_Abb[(size_t)(t0 + 1) * MN_ + p0]     = a10 + b0;
            g_Abb[(size_t)(t0 + 1) * MN_ + p0 + 1] = a11 + b1;
        }
    } else {
        float (*tile)[33] = (float(*)[33])sh;
        int r = b - GEMM_BLKS;
        int g0 = (r % 25) * 32;
        int d0 = (r / 25) * 32;
        int tx = tid & 31, ty = tid >> 5;
#pragma unroll
        for (int i = ty; i < 32; i += 8) {
            int d = d0 + i, g = g0 + tx;
            if (d < D_IN) tile[i][tx] = Wd[d * M_ + g];
        }
        __syncthreads();
#pragma unroll
        for (int i = ty; i < 32; i += 8) {
            int g = g0 + i, d = d0 + tx;
            if (d < D_IN) g_WdT[g * D_IN + d] = tile[tx][i];
        }
    }
}

// ---------------------------------------------------------------------------
// Main sequential scan: single CTA, 416 threads (13 warps; tids 400-415
// dummies). Per step: per-warp candidate rows are L2-bulk-prefetched BEFORE
// bar1; after bar1 the argmax resolve runs first and the winning row's LDGs
// issue into shadow regs d0-d3 before the min/tie logic; jstar==jp steps
// reuse the live c-regs (zero memory wait).
// ---------------------------------------------------------------------------
__global__ void __launch_bounds__(416, 1)
scan_kernel(const float* __restrict__ bd, float* __restrict__ out) {
    __shared__ float lam_s[M_];
    __shared__ unsigned red_u[16], red_j[16], red_m[16];
    __shared__ int red_c[16];
    __shared__ float s_sigjp, s_tt;

    const int tid  = threadIdx.x;
    const int lane = tid & 31;
    const int wid  = tid >> 5;
    const bool act = tid < 400;
    const int  ft  = act ? tid : 0;          // safe load index for dummies

    // Zero the x_b / phi / psi tail (d_out is poisoned)
    for (int i = tid; i < 3 * MN_; i += 416) out[T_BATCH * D_IN + i] = 0.0f;
    __syncthreads();

    const float bdv0 = bd[tid];                                       // tid<784
    const float bdv1 = (tid < D_IN - 416) ? bd[tid + 416] : 0.0f;     // tid<368

    int   jp   = -1;
    float phiv = 0.0f;
    float wdP0 = 0.f, wdP1 = 0.f, gvalP = 0.f;
    float4 c0 = make_float4(0,0,0,0), c1 = make_float4(0,0,0,0);
    float4 c2 = make_float4(0,0,0,0), c3 = make_float4(0,0,0,0);
    const float4* ab0 = (const float4*)g_Abb;
    float4 a0 = ab0[ft], a1 = ab0[400+ft], a2 = ab0[800+ft], a3 = ab0[1200+ft];

    for (int t = 0; t < T_BATCH; ++t) {
        // Prefetch next abb row (consumed next step)
        const int tn = (t + 1 < T_BATCH) ? t + 1 : 0;
        const float4* ar = (const float4*)g_Abb + (unsigned)tn * 1600u;
        const float4 n0 = ar[ft], n1 = ar[400+ft], n2 = ar[800+ft], n3 = ar[1200+ft];

        // Deferred output store for step t-1
        if (t > 0) {
            out[(t-1) * D_IN + tid] =
                (gvalP > 0.f) ? fmaf(wdP0, gvalP, bdv0) : bdv0;
            if (tid < D_IN - 416)
                out[(t-1) * D_IN + tid + 416] =
                    (gvalP > 0.f) ? fmaf(wdP1, gvalP, bdv1) : bdv1;
        }

        // sigma (c* are exact zeros when no active one-hot); s[e] <-> j=16tid+e
        float s[16];
        s[0]=a0.x+c0.x;  s[1]=a0.y+c0.y;  s[2]=a0.z+c0.z;  s[3]=a0.w+c0.w;
        s[4]=a1.x+c1.x;  s[5]=a1.y+c1.y;  s[6]=a1.z+c1.z;  s[7]=a1.w+c1.w;
        s[8]=a2.x+c2.x;  s[9]=a2.y+c2.y;  s[10]=a2.z+c2.z; s[11]=a2.w+c2.w;
        s[12]=a3.x+c3.x; s[13]=a3.y+c3.y; s[14]=a3.z+c3.z; s[15]=a3.w+c3.w;

        // jp masking + publication: only the owner warp pays (uniform branch)
        float msk[16];
#pragma unroll
        for (int e = 0; e < 16; ++e) msk[e] = s[e];
        if (jp >= 0 && wid == (jp >> 9)) {
            const int jd = jp - 16 * tid;
            if (jd >= 0 && jd < 16) {
                float v = s[0];
#pragma unroll
                for (int e = 1; e < 16; ++e) v = (jd == e) ? s[e] : v;
                s_sigjp = v;
#pragma unroll
                for (int e = 0; e < 16; ++e) if (jd == e) msk[e] = NEG_INF;
            }
        }

        // Masked group maxes (lam) + raw global min
        float gmA = fmaxf(fmaxf(fmaxf(msk[0],msk[1]),fmaxf(msk[2],msk[3])),
                          fmaxf(fmaxf(msk[4],msk[5]),fmaxf(msk[6],msk[7])));
        float gmB = fmaxf(fmaxf(fmaxf(msk[8],msk[9]),fmaxf(msk[10],msk[11])),
                          fmaxf(fmaxf(msk[12],msk[13]),fmaxf(msk[14],msk[15])));
        float vmin = fminf(
            fminf(fminf(fminf(s[0],s[1]),fminf(s[2],s[3])),
                  fminf(fminf(s[4],s[5]),fminf(s[6],s[7]))),
            fminf(fminf(fminf(s[8],s[9]),fminf(s[10],s[11])),
                  fminf(fminf(s[12],s[13]),fminf(s[14],s[15]))));
        if (!act) { gmA = NEG_INF; gmB = NEG_INF; vmin = POS_INF; }
        if (act) { lam_s[2*tid] = gmA; lam_s[2*tid+1] = gmB; }

        // Warp reduction: max value (argmax) + min; single-ballot election
        const float tmax = fmaxf(gmA, gmB);
        const unsigned wu = __reduce_max_sync(0xFFFFFFFFu, fmap(__float_as_uint(tmax)));
        const unsigned wm = __reduce_min_sync(0xFFFFFFFFu, fmap(__float_as_uint(vmin)));
        const float wv = funmap(wu);
        const unsigned ball = __ballot_sync(0xFFFFFFFFu, tmax == wv);
        if (lane == __ffs(ball) - 1) {
            // Lowest lane = lowest j base; local first index = global tie rule
            int idx = 15;
#pragma unroll
            for (int e = 14; e >= 0; --e) idx = (msk[e] == wv) ? e : idx;
            const unsigned cj = (unsigned)(16 * tid + idx);
            red_j[wid] = cj;
            // L2 bulk-prefetch this warp's candidate row NOW (~250+ cyc head
            // start; winner M1 is always among the 13 candidates)
            const void* rp = (const void*)(g_WbT + (size_t)cj * MN_);
            asm volatile("cp.async.bulk.prefetch.L2.global [%0], %1;"
                         :: "l"(rp), "r"((unsigned)(MN_ * 4)) : "memory");
        }
        if (lane == 0) { red_u[wid] = wu; red_m[wid] = wm; }
        __syncthreads();                                       // bar1

        // Redundant resolve, identical in every warp — argmax FIRST
        const bool v13 = (lane < 13);
        const unsigned ru = v13 ? red_u[lane] : 0u;
        const unsigned rj = v13 ? red_j[lane] : 0xFFFFFFFFu;
        const unsigned gu = __reduce_max_sync(0xFFFFFFFFu, ru);
        const unsigned gj = __reduce_min_sync(0xFFFFFFFFu, (ru == gu) ? rj : 0xFFFFFFFFu);
        const int   M1  = (int)gj;
        const float vM1 = funmap(gu);        // sigma[M1], bit-exact

        // ---- EARLY fetch of row M1 into shadow regs (before min/tie) ----
        float4 d0, d1, d2, d3;
        {
            const float4* wr =
                (const float4*)((const char*)g_WbT + (unsigned)M1 * (unsigned)(MN_ * 4));
            d0 = wr[ft]; d1 = wr[400+ft]; d2 = wr[800+ft]; d3 = wr[1200+ft];
        }

        const unsigned rm = v13 ? red_m[lane] : 0xFFFFFFFFu;
        const unsigned gmn = __reduce_min_sync(0xFFFFFFFFu, rm);
        const float smin = funmap(gmn);
        int   jstar = M1;
        float sj    = vM1;
        float sigjp = 0.0f;
        if (jp >= 0) {
            sigjp = s_sigjp;
            const float v1 = (vM1 - smin) + 1.0f;
            const float pv = (1.0f - phiv) * ((sigjp - smin) + 1.0f);
            if (pv > v1 || (pv == v1 && jp < M1)) { jstar = jp; sj = sigjp; }
        }

        const int gcol = jstar >> 3;
        const float wd0 = g_WdT[gcol * D_IN + tid];
        const float wd1 = (tid < D_IN - 416) ? g_WdT[gcol * D_IN + tid + 416] : 0.f;

        if (tid == 0) s_tt = tanhf(sj);      // scalarized; read after bar2

        // Rank of q among lam (stable top-k), pi-space
        const int q  = (int)((unsigned)jstar % 800u);
        const int gp = jp >> 3;              // meaningful only when jp>=0
        float pvp = 0.0f;
        if (jp >= 0) pvp = (1.0f - phiv) * ((sigjp - smin) + 1.0f);
        float lamq = (lam_s[q] - smin) + 1.0f;
        if (jp >= 0 && q == gp) lamq = fmaxf(lamq, pvp);
        int f = 0;
        if (act) {
            const int mA = 2 * tid, mB = 2 * tid + 1;
            if (mA != q) {
                float lm = (gmA - smin) + 1.0f;
                if (jp >= 0 && mA == gp) lm = fmaxf(lm, pvp);
                f += (lm > lamq) || (lm == lamq && mA < q);
            }
            if (mB != q) {
                float lm = (gmB - smin) + 1.0f;
                if (jp >= 0 && mB == gp) lm = fmaxf(lm, pvp);
                f += (lm > lamq) || (lm == lamq && mB < q);
            }
        }
        const int cw = __reduce_add_sync(0xFFFFFFFFu, f);
        if (lane == 0) red_c[wid] = cw;
        __syncthreads();                                       // bar2
        const int cnt = __reduce_add_sync(0xFFFFFFFFu, v13 ? red_c[lane] : 0);

        // Winner iff rank < K and tanh positive (tanh>0 <=> sj>0)
        const bool win = (cnt < K_) && (sj > 0.0f);
        const float yv = win ? s_tt : 0.0f;

        wdP0 = wd0; wdP1 = wd1; gvalP = yv;
        if (win) {
            if (jstar != jp) { c0 = d0; c1 = d1; c2 = d2; c3 = d3; }
            // jstar == jp: c-regs already hold row jp — zero memory wait
            jp = jstar; phiv = yv;
        } else {
            jp = -1; phiv = 0.0f;
            c0 = make_float4(0,0,0,0); c1 = make_float4(0,0,0,0);
            c2 = make_float4(0,0,0,0); c3 = make_float4(0,0,0,0);
        }
        a0 = n0; a1 = n1; a2 = n2; a3 = n3;
    }

    // Final deferred store (t = T_BATCH-1)
    out[(T_BATCH-1) * D_IN + tid] =
        (gvalP > 0.f) ? fmaf(wdP0, gvalP, bdv0) : bdv0;
    if (tid < D_IN - 416)
        out[(T_BATCH-1) * D_IN + tid + 416] =
            (gvalP > 0.f) ? fmaf(wdP1, gvalP, bdv1) : bdv1;

    // Final outputs: x_b (exactly one-hot 1.0), phi, psis[-1]
    if (tid == 0 && jp >= 0) {
        out[T_BATCH * D_IN + jp]           = 1.0f;   // x_b
        out[T_BATCH * D_IN + MN_ + jp]     = phiv;   // phi
        out[T_BATCH * D_IN + 2 * MN_ + jp] = phiv;   // psis[-1]
    }
}

// ---------------------------------------------------------------------------
extern "C" void kernel_launch(void* const* d_in, const int* in_sizes, int n_in,
                              void* d_out, int out_size) {
    const float* X  = (const float*)d_in[0];
    const float* Wa = (const float*)d_in[1];
    const float* ba = (const float*)d_in[2];
    const float* Wb = (const float*)d_in[3];
    const float* bb = (const float*)d_in[4];
    const float* Wd = (const float*)d_in[5];
    const float* bd = (const float*)d_in[6];
    float* out = (float*)d_out;

    prep_kernel<<<PREP_BLKS, 256>>>(X, Wa, ba, Wd, Wb, bb);
    scan_kernel<<<1, 416>>>(bd, out);
}

// round 16
// speedup vs baseline: 1.2614x; 1.2614x over previous
#include <cuda_runtime.h>
#include <cstdint>

#define T_BATCH 256
#define D_IN    784
#define M_      800
#define N_      8
#define K_      25
#define MN_     6400
#define NEG_INF (-3.402823466e38f)
#define POS_INF (3.402823466e38f)

// Scratch (allocation-free rule: __device__ globals)
__device__ float g_WbT[(size_t)MN_ * MN_];     // W_b^T, rows sigma-permuted (164 MB)
__device__ float g_Abb[(size_t)T_BATCH * MN_]; // abb[t][sig(j)] = a[t][j%800]+bb[j]
__device__ float g_WdT[M_ * D_IN];             // W_d transposed

// Within-row permutation: j = 16q + 4k + i  ->  pos = 1600k + 4q + i.
// Thread q owns 16 consecutive j via 4 coalesced float4 loads at
// positions {q, 400+q, 800+q, 1200+q}.
__device__ __forceinline__ int sig(int j) {
    return ((j >> 2) & 3) * 1600 + ((j >> 4) << 2) + (j & 3);
}

// Monotone float<->uint order mapping (no NaNs in this workload)
__device__ __forceinline__ unsigned fmap(unsigned b) {
    return (b & 0x80000000u) ? ~b : (b | 0x80000000u);
}
__device__ __forceinline__ float funmap(unsigned u) {
    unsigned b = (u & 0x80000000u) ? (u & 0x7FFFFFFFu) : ~u;
    return __uint_as_float(b);
}

// ---------------------------------------------------------------------------
// Mega prep kernel (layout-permuted stores; same DRAM byte totals)
// ---------------------------------------------------------------------------
#define GEMM_BLKS 200
#define WD_BLKS   625
#define WB_BASE   (GEMM_BLKS + WD_BLKS)
#define PREP_BLKS (WB_BASE + 200 * 200)
#define TS 36   // 144B row stride: 16B-aligned rows for float4 LDS/STS

__global__ void __launch_bounds__(256)
prep_kernel(const float* __restrict__ X, const float* __restrict__ Wa,
            const float* __restrict__ ba, const float* __restrict__ Wd,
            const float* __restrict__ Wb, const float* __restrict__ bb) {
    __shared__ __align__(16) float sh[2 * 32 * TS];
    const int b = blockIdx.x;
    const int tid = threadIdx.x;

    if (b >= WB_BASE) {
        // W_b transpose with sigma-permuted in-row (j) index
        float (*tile)[33] = (float(*)[33])sh;
        int b2 = b - WB_BASE;
        int bx = b2 % 200, by = b2 / 200;
        int tx = tid & 31, ty = tid >> 5;
        int x = bx * 32 + tx;
        int y0 = by * 32;
#pragma unroll
        for (int i = ty; i < 32; i += 8)
            tile[i][tx] = Wb[(size_t)(y0 + i) * MN_ + x];
        __syncthreads();
        int x2 = by * 32 + tx;       // in-row (j) index before permutation
        int y2 = bx * 32;            // row (W column) index
        int px = sig(x2);
#pragma unroll
        for (int i = ty; i < 32; i += 8)
            g_WbT[(size_t)(y2 + i) * MN_ + px] = tile[tx][i];
    } else if (b < GEMM_BLKS) {
        float (*Xs)[TS] = (float(*)[TS])sh;
        float (*Ws)[TS] = (float(*)[TS])(sh + 32 * TS);
        const int bm = b % 25, bt = b / 25;
        const int lrow = tid >> 3, lc4 = tid & 7;
        const int tx = tid & 15, ty = tid >> 4;
        float c00 = 0.f, c01 = 0.f, c10 = 0.f, c11 = 0.f;
        for (int k0 = 0; k0 < D_IN; k0 += 32) {
            int kc = k0 + lc4 * 4;
            float4 xv = (kc + 3 < D_IN)
                ? *(const float4*)(X + (bt * 32 + lrow) * D_IN + kc)
                : make_float4(0.f, 0.f, 0.f, 0.f);
            float4 wv = (kc + 3 < D_IN)
                ? *(const float4*)(Wa + (bm * 32 + lrow) * D_IN + kc)
                : make_float4(0.f, 0.f, 0.f, 0.f);
            __syncthreads();
            *(float4*)&Xs[lrow][lc4 * 4] = xv;
            *(float4*)&Ws[lrow][lc4 * 4] = wv;
            __syncthreads();
#pragma unroll
            for (int k = 0; k < 32; k += 4) {
                float4 x0 = *(const float4*)&Xs[2 * ty][k];
                float4 x1 = *(const float4*)&Xs[2 * ty + 1][k];
                float4 w0 = *(const float4*)&Ws[2 * tx][k];
                float4 w1 = *(const float4*)&Ws[2 * tx + 1][k];
                c00 = fmaf(x0.x, w0.x, c00); c00 = fmaf(x0.y, w0.y, c00);
                c00 = fmaf(x0.z, w0.z, c00); c00 = fmaf(x0.w, w0.w, c00);
                c01 = fmaf(x0.x, w1.x, c01); c01 = fmaf(x0.y, w1.y, c01);
                c01 = fmaf(x0.z, w1.z, c01); c01 = fmaf(x0.w, w1.w, c01);
                c10 = fmaf(x1.x, w0.x, c10); c10 = fmaf(x1.y, w0.y, c10);
                c10 = fmaf(x1.z, w0.z, c10); c10 = fmaf(x1.w, w0.w, c10);
                c11 = fmaf(x1.x, w1.x, c11); c11 = fmaf(x1.y, w1.y, c11);
                c11 = fmaf(x1.z, w1.z, c11); c11 = fmaf(x1.w, w1.w, c11);
            }
        }
        int m0 = bm * 32 + 2 * tx, t0 = bt * 32 + 2 * ty;   // m0 even
        float a00 = c00 + ba[m0],     a01 = c01 + ba[m0 + 1];
        float a10 = c10 + ba[m0],     a11 = c11 + ba[m0 + 1];
#pragma unroll
        for (int k = 0; k < 8; ++k) {
            int j0 = m0 + 800 * k;
            int p0 = sig(j0);            // sig(j0+1) == p0+1 (j0 even)
            float b0 = bb[j0], b1 = bb[j0 + 1];
            g_Abb[(size_t)t0 * MN_ + p0]           = a00 + b0;
            g_Abb[(size_t)t0 * MN_ + p0 + 1]       = a01 + b1;
            g_Abb[(size_t)(t0 + 1) * MN_ + p0]     = a10 + b0;
            g_Abb[(size_t)(t0 + 1) * MN_ + p0 + 1] = a11 + b1;
        }
    } else {
        float (*tile)[33] = (float(*)[33])sh;
        int r = b - GEMM_BLKS;
        int g0 = (r % 25) * 32;
        int d0 = (r / 25) * 32;
        int tx = tid & 31, ty = tid >> 5;
#pragma unroll
        for (int i = ty; i < 32; i += 8) {
            int d = d0 + i, g = g0 + tx;
            if (d < D_IN) tile[i][tx] = Wd[d * M_ + g];
        }
        __syncthreads();
#pragma unroll
        for (int i = ty; i < 32; i += 8) {
            int g = g0 + i, d = d0 + tx;
            if (d < D_IN) g_WdT[g * D_IN + d] = tile[tx][i];
        }
    }
}

// ---------------------------------------------------------------------------
// Main sequential scan: single CTA, 416 threads (13 warps; tids 400-415
// dummies). R14 structure + two zero-cost changes: (1) after bar1 the argmax
// resolves first and row M1's LDGs issue straight into c0-c3 (no shadow
// regs); rare tie-win (jstar==jp!=M1) reloads row jp from L1. (2) tanh moved
// after bar2, win-steps only — off the bar2 critical path. NO L2 prefetches.
// ---------------------------------------------------------------------------
__global__ void __launch_bounds__(416, 1)
scan_kernel(const float* __restrict__ bd, float* __restrict__ out) {
    __shared__ float lam_s[M_];
    __shared__ unsigned red_u[16], red_j[16], red_m[16];
    __shared__ int red_c[16];
    __shared__ float s_sigjp;

    const int tid  = threadIdx.x;
    const int lane = tid & 31;
    const int wid  = tid >> 5;
    const bool act = tid < 400;
    const int  ft  = act ? tid : 0;          // safe load index for dummies

    // Zero the x_b / phi / psi tail (d_out is poisoned)
    for (int i = tid; i < 3 * MN_; i += 416) out[T_BATCH * D_IN + i] = 0.0f;
    __syncthreads();

    const float bdv0 = bd[tid];                                       // tid<784
    const float bdv1 = (tid < D_IN - 416) ? bd[tid + 416] : 0.0f;     // tid<368

    int   jp   = -1;
    float phiv = 0.0f;
    float wdP0 = 0.f, wdP1 = 0.f, gvalP = 0.f;
    float4 c0 = make_float4(0,0,0,0), c1 = make_float4(0,0,0,0);
    float4 c2 = make_float4(0,0,0,0), c3 = make_float4(0,0,0,0);
    const float4* ab0 = (const float4*)g_Abb;
    float4 a0 = ab0[ft], a1 = ab0[400+ft], a2 = ab0[800+ft], a3 = ab0[1200+ft];

    for (int t = 0; t < T_BATCH; ++t) {
        // Prefetch next abb row (consumed next step)
        const int tn = (t + 1 < T_BATCH) ? t + 1 : 0;
        const float4* ar = (const float4*)g_Abb + (unsigned)tn * 1600u;
        const float4 n0 = ar[ft], n1 = ar[400+ft], n2 = ar[800+ft], n3 = ar[1200+ft];

        // Deferred output store for step t-1
        if (t > 0) {
            out[(t-1) * D_IN + tid] =
                (gvalP > 0.f) ? fmaf(wdP0, gvalP, bdv0) : bdv0;
            if (tid < D_IN - 416)
                out[(t-1) * D_IN + tid + 416] =
                    (gvalP > 0.f) ? fmaf(wdP1, gvalP, bdv1) : bdv1;
        }

        // sigma (c* are exact zeros when no active one-hot); s[e] <-> j=16tid+e
        float s[16];
        s[0]=a0.x+c0.x;  s[1]=a0.y+c0.y;  s[2]=a0.z+c0.z;  s[3]=a0.w+c0.w;
        s[4]=a1.x+c1.x;  s[5]=a1.y+c1.y;  s[6]=a1.z+c1.z;  s[7]=a1.w+c1.w;
        s[8]=a2.x+c2.x;  s[9]=a2.y+c2.y;  s[10]=a2.z+c2.z; s[11]=a2.w+c2.w;
        s[12]=a3.x+c3.x; s[13]=a3.y+c3.y; s[14]=a3.z+c3.z; s[15]=a3.w+c3.w;

        // jp masking + publication: only the owner warp pays (uniform branch)
        float msk[16];
#pragma unroll
        for (int e = 0; e < 16; ++e) msk[e] = s[e];
        if (jp >= 0 && wid == (jp >> 9)) {
            const int jd = jp - 16 * tid;
            if (jd >= 0 && jd < 16) {
                float v = s[0];
#pragma unroll
                for (int e = 1; e < 16; ++e) v = (jd == e) ? s[e] : v;
                s_sigjp = v;
#pragma unroll
                for (int e = 0; e < 16; ++e) if (jd == e) msk[e] = NEG_INF;
            }
        }

        // Masked group maxes (lam) + raw global min
        float gmA = fmaxf(fmaxf(fmaxf(msk[0],msk[1]),fmaxf(msk[2],msk[3])),
                          fmaxf(fmaxf(msk[4],msk[5]),fmaxf(msk[6],msk[7])));
        float gmB = fmaxf(fmaxf(fmaxf(msk[8],msk[9]),fmaxf(msk[10],msk[11])),
                          fmaxf(fmaxf(msk[12],msk[13]),fmaxf(msk[14],msk[15])));
        float vmin = fminf(
            fminf(fminf(fminf(s[0],s[1]),fminf(s[2],s[3])),
                  fminf(fminf(s[4],s[5]),fminf(s[6],s[7]))),
            fminf(fminf(fminf(s[8],s[9]),fminf(s[10],s[11])),
                  fminf(fminf(s[12],s[13]),fminf(s[14],s[15]))));
        if (!act) { gmA = NEG_INF; gmB = NEG_INF; vmin = POS_INF; }
        if (act) { lam_s[2*tid] = gmA; lam_s[2*tid+1] = gmB; }

        // Warp reduction: max value (argmax) + min; single-ballot election
        const float tmax = fmaxf(gmA, gmB);
        const unsigned wu = __reduce_max_sync(0xFFFFFFFFu, fmap(__float_as_uint(tmax)));
        const unsigned wm = __reduce_min_sync(0xFFFFFFFFu, fmap(__float_as_uint(vmin)));
        const float wv = funmap(wu);
        const unsigned ball = __ballot_sync(0xFFFFFFFFu, tmax == wv);
        if (lane == __ffs(ball) - 1) {
            // Lowest lane = lowest j base; local first index = global tie rule
            int idx = 15;
#pragma unroll
            for (int e = 14; e >= 0; --e) idx = (msk[e] == wv) ? e : idx;
            red_j[wid] = (unsigned)(16 * tid + idx);
        }
        if (lane == 0) { red_u[wid] = wu; red_m[wid] = wm; }
        __syncthreads();                                       // bar1

        // Redundant resolve, identical in every warp — argmax FIRST
        const bool v13 = (lane < 13);
        const unsigned ru = v13 ? red_u[lane] : 0u;
        const unsigned rj = v13 ? red_j[lane] : 0xFFFFFFFFu;
        const unsigned gu = __reduce_max_sync(0xFFFFFFFFu, ru);
        const unsigned gj = __reduce_min_sync(0xFFFFFFFFu, (ru == gu) ? rj : 0xFFFFFFFFu);
        const int   M1  = (int)gj;
        const float vM1 = funmap(gu);        // sigma[M1], bit-exact

        // ---- EARLY fetch of row M1 straight into c* (dead after sigma) ----
        {
            const float4* wr =
                (const float4*)((const char*)g_WbT + (unsigned)M1 * (unsigned)(MN_ * 4));
            c0 = wr[ft]; c1 = wr[400+ft]; c2 = wr[800+ft]; c3 = wr[1200+ft];
        }

        const unsigned rm = v13 ? red_m[lane] : 0xFFFFFFFFu;
        const unsigned gmn = __reduce_min_sync(0xFFFFFFFFu, rm);
        const float smin = funmap(gmn);
        int   jstar = M1;
        float sj    = vM1;
        float sigjp = 0.0f;
        if (jp >= 0) {
            sigjp = s_sigjp;
            const float v1 = (vM1 - smin) + 1.0f;
            const float pv = (1.0f - phiv) * ((sigjp - smin) + 1.0f);
            if (pv > v1 || (pv == v1 && jp < M1)) { jstar = jp; sj = sigjp; }
        }

        const int gcol = jstar >> 3;
        const float wd0 = g_WdT[gcol * D_IN + tid];
        const float wd1 = (tid < D_IN - 416) ? g_WdT[gcol * D_IN + tid + 416] : 0.f;

        // Rank of q among lam (stable top-k), pi-space
        const int q  = (int)((unsigned)jstar % 800u);
        const int gp = jp >> 3;              // meaningful only when jp>=0
        float pvp = 0.0f;
        if (jp >= 0) pvp = (1.0f - phiv) * ((sigjp - smin) + 1.0f);
        float lamq = (lam_s[q] - smin) + 1.0f;
        if (jp >= 0 && q == gp) lamq = fmaxf(lamq, pvp);
        int f = 0;
        if (act) {
            const int mA = 2 * tid, mB = 2 * tid + 1;
            if (mA != q) {
                float lm = (gmA - smin) + 1.0f;
                if (jp >= 0 && mA == gp) lm = fmaxf(lm, pvp);
                f += (lm > lamq) || (lm == lamq && mA < q);
            }
            if (mB != q) {
                float lm = (gmB - smin) + 1.0f;
                if (jp >= 0 && mB == gp) lm = fmaxf(lm, pvp);
                f += (lm > lamq) || (lm == lamq && mB < q);
            }
        }
        const int cw = __reduce_add_sync(0xFFFFFFFFu, f);
        if (lane == 0) red_c[wid] = cw;
        __syncthreads();                                       // bar2
        const int cnt = __reduce_add_sync(0xFFFFFFFFu, v13 ? red_c[lane] : 0);

        // Winner iff rank < K and tanh positive (tanh>0 <=> sj>0).
        // tanh AFTER bar2, win-steps only: consumers (phiv at next resolve,
        // gvalP at next deferred store) have ~700 cyc slack -> overlaps the
        // in-flight W-row fetch instead of blocking bar2.
        const bool win = (cnt < K_) && (sj > 0.0f);
        float yv = 0.0f;
        if (win) yv = tanhf(sj);

        wdP0 = wd0; wdP1 = wd1; gvalP = yv;
        if (win) {
            if (jstar != M1) {
                // tie-win on jp: row jp was loaded last step -> L1-resident
                const float4* w2 =
                    (const float4*)((const char*)g_WbT + (unsigned)jstar * (unsigned)(MN_ * 4));
                c0 = w2[ft]; c1 = w2[400+ft]; c2 = w2[800+ft]; c3 = w2[1200+ft];
            }
            jp = jstar; phiv = yv;
        } else {
            jp = -1; phiv = 0.0f;
            c0 = make_float4(0,0,0,0); c1 = make_float4(0,0,0,0);
            c2 = make_float4(0,0,0,0); c3 = make_float4(0,0,0,0);
        }
        a0 = n0; a1 = n1; a2 = n2; a3 = n3;
    }

    // Final deferred store (t = T_BATCH-1)
    out[(T_BATCH-1) * D_IN + tid] =
        (gvalP > 0.f) ? fmaf(wdP0, gvalP, bdv0) : bdv0;
    if (tid < D_IN - 416)
        out[(T_BATCH-1) * D_IN + tid + 416] =
            (gvalP > 0.f) ? fmaf(wdP1, gvalP, bdv1) : bdv1;

    // Final outputs: x_b (exactly one-hot 1.0), phi, psis[-1]
    if (tid == 0 && jp >= 0) {
        out[T_BATCH * D_IN + jp]           = 1.0f;   // x_b
        out[T_BATCH * D_IN + MN_ + jp]     = phiv;   // phi
        out[T_BATCH * D_IN + 2 * MN_ + jp] = phiv;   // psis[-1]
    }
}

// ---------------------------------------------------------------------------
extern "C" void kernel_launch(void* const* d_in, const int* in_sizes, int n_in,
                              void* d_out, int out_size) {
    const float* X  = (const float*)d_in[0];
    const float* Wa = (const float*)d_in[1];
    const float* ba = (const float*)d_in[2];
    const float* Wb = (const float*)d_in[3];
    const float* bb = (const float*)d_in[4];
    const float* Wd = (const float*)d_in[5];
    const float* bd = (const float*)d_in[6];
    float* out = (float*)d_out;

    prep_kernel<<<PREP_BLKS, 256>>>(X, Wa, ba, Wd, Wb, bb);
    scan_kernel<<<1, 416>>>(bd, out);
}